// round 15
// baseline (speedup 1.0000x reference)
#include <cuda_runtime.h>
#include <cuda_bf16.h>
#include <math.h>
#include <stdint.h>

#define BB 4
#define NN 4096
#define FF 128
#define SS 1024
#define KK 64
#define CC 256
#define MTOT (BB*SS*KK)
#define EPSF 1e-5f

// ---------------- device scratch ----------------
__device__ int   g_cent[BB*SS];
__device__ int   g_group[BB*SS*KK];
__device__ float g_P[BB*NN*CC];
__device__ float g_Q[BB*SS*CC];
__device__ float g_X[BB*SS*KK*CC];       // pre-transformed layer-2 input (256 MB)
__device__ float g_W2rt[CC*CC];
__device__ float g_sum1[CC], g_sq1[CC], g_sum2[CC], g_sq2[CC];
__device__ float g_mx[BB*SS*CC], g_mn[BB*SS*CC];

__device__ __forceinline__ float to_tf32(float x){
    unsigned u;
    asm("cvt.rna.tf32.f32 %0, %1;" : "=r"(u) : "f"(x));
    return __uint_as_float(u);
}
__device__ __forceinline__ uint32_t smem_u32(const void* p){
    uint32_t a;
    asm("{ .reg .u64 t; cvta.to.shared.u64 t, %1; cvt.u32.u64 %0, t; }" : "=r"(a) : "l"(p));
    return a;
}
__device__ __forceinline__ void cp_async16(uint32_t saddr, const void* gmem){
    asm volatile("cp.async.cg.shared.global [%0], [%1], 16;" :: "r"(saddr), "l"(gmem));
}
// packed f32x2 helpers (per-component rounding == scalar FADD/FMUL/FFMA)
__device__ __forceinline__ unsigned long long pk2(float lo, float hi){
    unsigned long long r;
    asm("mov.b64 %0, {%1,%2};" : "=l"(r) : "f"(lo), "f"(hi));
    return r;
}
__device__ __forceinline__ void upk2(unsigned long long v, float& lo, float& hi){
    asm("mov.b64 {%0,%1}, %2;" : "=f"(lo), "=f"(hi) : "l"(v));
}
__device__ __forceinline__ unsigned long long add2(unsigned long long a, unsigned long long b){
    unsigned long long r; asm("add.rn.f32x2 %0,%1,%2;" : "=l"(r) : "l"(a), "l"(b)); return r;
}
__device__ __forceinline__ unsigned long long mul2(unsigned long long a, unsigned long long b){
    unsigned long long r; asm("mul.rn.f32x2 %0,%1,%2;" : "=l"(r) : "l"(a), "l"(b)); return r;
}
__device__ __forceinline__ unsigned long long fma2(unsigned long long a, unsigned long long b, unsigned long long c){
    unsigned long long r; asm("fma.rn.f32x2 %0,%1,%2,%3;" : "=l"(r) : "l"(a), "l"(b), "l"(c)); return r;
}

// ---------------- mega1 (512 thr): FPS [0..3] || pgemm [4..1027] || misc [1028] ----------------
extern __shared__ char mega_smem[];

__device__ void fps_body(const float* __restrict__ pos, int b){
    // layout: slots[2][16] u64 (256B) | s_pos | s_sel | s_mask
    unsigned long long* slots = (unsigned long long*)mega_smem;
    float*    s_pos  = (float*)(mega_smem + 256);
    int*      s_sel  = (int*)(mega_smem + 256 + NN*3*4);
    unsigned* s_mask = (unsigned*)(mega_smem + 256 + NN*3*4 + SS*4);
    volatile unsigned long long* vslots = (volatile unsigned long long*)slots;
    int t = threadIdx.x;
    const float* bp = pos + (size_t)b*NN*3;

    for (int i=t; i<NN*3; i+=512) s_pos[i] = bp[i];
    if (t < 32) slots[t] = 0ull;
    if (t==0) s_sel[0] = 0;
    __syncthreads();

    unsigned long long px2[4], py2[4], pz2[4];
    float dd[8];
    float qx=s_pos[0], qy=s_pos[1], qz=s_pos[2];
    float vmaxf = 0.f;
#pragma unroll
    for (int jp=0;jp<4;jp++){
        int i0 = t + 512*(2*jp), i1 = t + 512*(2*jp+1);
        float x0=s_pos[3*i0], y0=s_pos[3*i0+1], z0=s_pos[3*i0+2];
        float x1=s_pos[3*i1], y1=s_pos[3*i1+1], z1=s_pos[3*i1+2];
        px2[jp]=pk2(x0,x1); py2[jp]=pk2(y0,y1); pz2[jp]=pk2(z0,z1);
        float dx0=x0-qx, dy0=y0-qy, dz0=z0-qz;
        float dx1=x1-qx, dy1=y1-qy, dz1=z1-qz;
        dd[2*jp]   = dx0*dx0 + dy0*dy0 + dz0*dz0;
        dd[2*jp+1] = dx1*dx1 + dy1*dy1 + dz1*dz1;
        vmaxf = fmaxf(vmaxf, fmaxf(dd[2*jp], dd[2*jp+1]));
    }

    int wid = t >> 5, lane = t & 31;
#pragma unroll 1
    for (int it=1; it<SS; it++){
        unsigned tag = (unsigned)it & 0x3FFu;
        int par = it & 1;
        unsigned ub = __float_as_uint(vmaxf);            // dists >= 0: bits order-monotone
        unsigned rv = __reduce_max_sync(0xffffffffu, ub);
        unsigned cand = 0u;
        if (ub == rv){
            int idx = 0;
#pragma unroll
            for (int j=7;j>=0;j--)
                if (__float_as_uint(dd[j]) == rv) idx = t + 512*j;   // ends at smallest j
            cand = 0xFFFu & ~(unsigned)idx;
        }
        unsigned ri = __reduce_max_sync(0xffffffffu, cand);  // max ~idx == min idx
        if (lane==0)
            vslots[par*16 + wid] = ((unsigned long long)rv << 22)
                                 | ((unsigned long long)ri << 10)
                                 | (unsigned long long)tag;
        // EVERY warp: lanes 0-15 poll one slot each (parallel), 2x REDUX, shfl-broadcast
        unsigned mi = 0u;
        if (lane < 16){
            unsigned long long v;
            do { v = vslots[par*16 + lane]; } while ((unsigned)(v & 0x3FFull) != tag);
            unsigned val = (unsigned)(v >> 22);
            unsigned rid = (unsigned)((v >> 10) & 0xFFFull);
            unsigned mv = __reduce_max_sync(0xFFFFu, val);
            unsigned c2 = (val==mv) ? rid : 0u;
            mi = __reduce_max_sync(0xFFFFu, c2);
        }
        mi = __shfl_sync(0xffffffffu, mi, 0);
        int nxt = (int)(0xFFFu & ~mi);
        if (t==0) s_sel[it] = nxt;
        float cx=s_pos[3*nxt], cy=s_pos[3*nxt+1], cz=s_pos[3*nxt+2];
        unsigned long long ncx=pk2(-cx,-cx), ncy=pk2(-cy,-cy), ncz=pk2(-cz,-cz);
        float nv = 0.f;
#pragma unroll
        for (int jp=0;jp<4;jp++){
            unsigned long long dx2=add2(px2[jp],ncx);
            unsigned long long dy2=add2(py2[jp],ncy);
            unsigned long long dz2=add2(pz2[jp],ncz);
            unsigned long long d2 = mul2(dx2,dx2);
            d2 = fma2(dy2,dy2,d2);
            d2 = fma2(dz2,dz2,d2);
            float dlo,dhi; upk2(d2,dlo,dhi);
            float a = fminf(dd[2*jp],   dlo);
            float c = fminf(dd[2*jp+1], dhi);
            dd[2*jp]=a; dd[2*jp+1]=c;
            nv = fmaxf(nv, fmaxf(a,c));
        }
        vmaxf = nv;
    }
    __syncthreads();
    if (t < NN/32) s_mask[t]=0u;
    __syncthreads();
    for (int i=t; i<SS; i+=512) atomicOr(&s_mask[s_sel[i]>>5], 1u<<(s_sel[i]&31));
    __syncthreads();
    for (int i=t; i<SS; i+=512){
        int idx=s_sel[i];
        int w=idx>>5, r=0;
        for (int ww=0; ww<w; ww++) r += __popc(s_mask[ww]);
        r += __popc(s_mask[w] & ((1u<<(idx&31))-1u));
        g_cent[b*SS + r] = idx;
    }
}

__device__ void pgemm_body(const float* __restrict__ feat, const float* __restrict__ W1, int blk){
    float (*sf)[FF] = (float (*)[FF])mega_smem;
    int r0 = blk*16, t = threadIdx.x;
    for (int i=t; i<16*FF; i+=512)
        sf[i/FF][i%FF] = to_tf32(feat[(size_t)(r0 + i/FF)*FF + (i%FF)]);
    __syncthreads();
    int h = t >> 8;          // row half
    int o = t & 255;
    const float* wrow = W1 + (size_t)o*(2*FF);
    float acc[8];
#pragma unroll
    for (int r=0;r<8;r++) acc[r]=0.f;
    for (int c4=0; c4<FF; c4+=4){
        float4 wa = *(const float4*)(wrow + c4);
        float4 wb = *(const float4*)(wrow + FF + c4);
        float w0 = to_tf32(wa.x)+to_tf32(wb.x);
        float w1 = to_tf32(wa.y)+to_tf32(wb.y);
        float w2 = to_tf32(wa.z)+to_tf32(wb.z);
        float w3 = to_tf32(wa.w)+to_tf32(wb.w);
#pragma unroll
        for (int r=0;r<8;r++){
            acc[r]=fmaf(sf[h*8+r][c4+0], w0, acc[r]);
            acc[r]=fmaf(sf[h*8+r][c4+1], w1, acc[r]);
            acc[r]=fmaf(sf[h*8+r][c4+2], w2, acc[r]);
            acc[r]=fmaf(sf[h*8+r][c4+3], w3, acc[r]);
        }
    }
#pragma unroll
    for (int r=0;r<8;r++) g_P[(size_t)(r0 + h*8 + r)*CC + o] = acc[r];
}

__device__ void misc_body(const float* __restrict__ W2){
    int t = threadIdx.x;
    for (int i=t*4; i<CC*CC; i+=512*4){
        float4 w = *(const float4*)(W2 + i);
        float4 v; v.x=to_tf32(w.x); v.y=to_tf32(w.y); v.z=to_tf32(w.z); v.w=to_tf32(w.w);
        *(float4*)(g_W2rt + i) = v;
    }
    if (t < CC){
        g_sum1[t]=0.f; g_sq1[t]=0.f; g_sum2[t]=0.f; g_sq2[t]=0.f;
    }
}

__global__ __launch_bounds__(512) void k_mega1(const float* __restrict__ pos,
                                               const float* __restrict__ feat,
                                               const float* __restrict__ W1,
                                               const float* __restrict__ W2){
    if (blockIdx.x < 4)          fps_body(pos, blockIdx.x);
    else if (blockIdx.x < 1028)  pgemm_body(feat, W1, blockIdx.x - 4);
    else                         misc_body(W2);
}

// ---------------- Q = tf32(centroid feat) @ tf32(W1a)^T ----------------
__global__ __launch_bounds__(256) void k_qgemm(const float* __restrict__ feat,
                                               const float* __restrict__ W1){
    __shared__ float sf[16][FF];
    int r0 = blockIdx.x*16, t = threadIdx.x;
    for (int i=t; i<16*FF; i+=256){
        int rr = r0 + i/FF;
        int b  = rr / SS;
        int cent = g_cent[rr];
        sf[i/FF][i%FF] = to_tf32(feat[(size_t)(b*NN + cent)*FF + (i%FF)]);
    }
    __syncthreads();
    int o = t;
    const float* wrow = W1 + (size_t)o*(2*FF);
    float acc[16];
#pragma unroll
    for (int r=0;r<16;r++) acc[r]=0.f;
    for (int c4=0; c4<FF; c4+=4){
        float4 wa = *(const float4*)(wrow + c4);
        float w0 = to_tf32(wa.x), w1 = to_tf32(wa.y), w2 = to_tf32(wa.z), w3 = to_tf32(wa.w);
#pragma unroll
        for (int r=0;r<16;r++){
            acc[r]=fmaf(sf[r][c4+0], w0, acc[r]);
            acc[r]=fmaf(sf[r][c4+1], w1, acc[r]);
            acc[r]=fmaf(sf[r][c4+2], w2, acc[r]);
            acc[r]=fmaf(sf[r][c4+3], w3, acc[r]);
        }
    }
#pragma unroll
    for (int r=0;r<16;r++) g_Q[(size_t)(r0+r)*CC + o] = acc[r];
}

// ---------------- KNN (256 thr) + fused BN1 stats ----------------
__global__ __launch_bounds__(256) void k_knns(const float* __restrict__ pos,
                                              const float* __restrict__ b1){
    __shared__ unsigned sbits[NN];
    __shared__ int shist[256];
    __shared__ unsigned s_prefix;
    __shared__ int s_want, s_cnt, s_eqcnt;
    __shared__ int s_eq[256];
    __shared__ int s_g[KK];
    int q = blockIdx.x, t = threadIdx.x;
    int b = q / SS;
    int c = g_cent[q];
    const float* bp = pos + (size_t)b*NN*3;
    float qx=bp[3*c], qy=bp[3*c+1], qz=bp[3*c+2];
    float qq = __fadd_rn(__fadd_rn(__fmul_rn(qx,qx), __fmul_rn(qy,qy)), __fmul_rn(qz,qz));

    for (int i=t; i<NN; i+=256){
        float x=bp[3*i], y=bp[3*i+1], z=bp[3*i+2];
        float pp = __fadd_rn(__fadd_rn(__fmul_rn(x,x), __fmul_rn(y,y)), __fmul_rn(z,z));
        float dot = __fadd_rn(__fadd_rn(__fmul_rn(qx,x), __fmul_rn(qy,y)), __fmul_rn(qz,z));
        float d = __fadd_rn(__fadd_rn(__fmul_rn(-2.0f, dot), qq), pp);
        unsigned u = __float_as_uint(d);
        u = (u & 0x80000000u) ? ~u : (u | 0x80000000u);
        sbits[i] = u;
    }
    if (t==0){ s_prefix=0u; s_want=KK; s_cnt=0; s_eqcnt=0; }
    __syncthreads();

    for (int pass=0; pass<4; pass++){
        int shift = 24 - 8*pass;
        shist[t]=0;
        __syncthreads();
        unsigned pref = s_prefix;
        for (int i=t; i<NN; i+=256){
            unsigned u = sbits[i];
            bool m = (pass==0) || ((u >> (shift+8)) == pref);
            if (m) atomicAdd(&shist[(u>>shift)&0xFFu], 1);
        }
        __syncthreads();
        if (t==0){
            int want=s_want, cum=0, bin;
            for (bin=0; bin<256; bin++){
                int h=shist[bin];
                if (cum+h >= want) break;
                cum += h;
            }
            s_want = want - cum;
            s_prefix = (s_prefix<<8) | (unsigned)bin;
        }
        __syncthreads();
    }
    unsigned T = s_prefix;
    for (int i=t; i<NN; i+=256){
        unsigned u = sbits[i];
        if (u < T){
            int p = atomicAdd(&s_cnt,1);
            g_group[q*KK + p] = i;
            s_g[p] = i;
        } else if (u == T){
            int p = atomicAdd(&s_eqcnt,1);
            if (p < 256) s_eq[p] = i;
        }
    }
    __syncthreads();
    if (t==0){
        int base = s_cnt;
        int nd   = KK - base;
        int ec   = s_eqcnt;
        if (ec <= 256){
            for (int r=0; r<nd; r++){
                int mi=r;
                for (int j=r+1; j<ec; j++) if (s_eq[j] < s_eq[mi]) mi=j;
                int tmp=s_eq[r]; s_eq[r]=s_eq[mi]; s_eq[mi]=tmp;
                g_group[q*KK + base + r] = s_eq[r];
                s_g[base + r] = s_eq[r];
            }
        } else {
            int w=nd, p=base;
            for (int i=0; i<NN && w>0; i++)
                if (sbits[i]==T){ g_group[q*KK + p] = i; s_g[p] = i; p++; w--; }
        }
    }
    __syncthreads();
    int o = t;
    float base = b1[o] - g_Q[(size_t)q*CC + o];
    float sum=0.f, sq=0.f;
    const float* Pb = g_P + (size_t)b*NN*CC;
#pragma unroll 4
    for (int k=0;k<KK;k++){
        float h = Pb[(size_t)s_g[k]*CC + o] + base;
        sum += h; sq = fmaf(h,h,sq);
    }
    atomicAdd(&g_sum1[o], sum);
    atomicAdd(&g_sq1[o],  sq);
}

// ---------------- X build: X[q][k][c] = tf32(relu(BN1(h1))) ----------------
__global__ __launch_bounds__(256) void k_xbuild(const float* __restrict__ b1,
                                                const float* __restrict__ gamma1,
                                                const float* __restrict__ beta1){
    __shared__ int s_g[KK];
    int q = blockIdx.x, t = threadIdx.x, b = q >> 10;
    if (t < KK) s_g[t] = g_group[q*KK + t];
    int c = t;
    float mean = g_sum1[c]*(1.0f/MTOT);
    float var  = g_sq1[c]*(1.0f/MTOT) - mean*mean;
    float a    = gamma1[c]*rsqrtf(var + EPSF);
    float ccv  = beta1[c] - mean*a;
    float d    = fmaf(a, b1[c] - g_Q[(size_t)q*CC + c], ccv);
    __syncthreads();
    const float* Pb = g_P + (size_t)b*NN*CC;
    float* Xq = g_X + (size_t)q*KK*CC;
#pragma unroll 4
    for (int k=0;k<KK;k++){
        float p = Pb[(size_t)s_g[k]*CC + c];
        Xq[k*CC + c] = to_tf32(fmaxf(fmaf(a, p, d), 0.f));
    }
}

// ---------------- layer2 GEMM: pure cp.async-pipelined mma.sync tf32 ----------------
// CTA = M128 x N128 (pair of groups x N-half); 3-stage smem ring; 2 CTAs/SM.
#define ASTR 36
#define STG (2*128*ASTR)          // floats per stage (A then B)
extern __shared__ float dyn_smem[];
__global__ __launch_bounds__(256, 2) void k_gemm2m(const float* __restrict__ b2){
    int t = threadIdx.x;
    int bid = blockIdx.x;
    int pair = bid >> 1;
    int nh   = bid & 1;
    int q0 = 2*pair;

    int lane = t & 31, wid = t >> 5;
    int warpM = wid >> 2, warpN = wid & 3;
    int r0 = warpM*64, n0l = warpN*32;
    int g = lane >> 2, tig = lane & 3;

    int row = t >> 1;
    int off = (t & 1) * 16;
    const float* Xr  = g_X + (size_t)pair*128*CC + (size_t)row*CC + off;
    const float* Wr2 = g_W2rt + (size_t)(nh*128 + row)*CC + off;
    uint32_t sbase = smem_u32(dyn_smem);
    uint32_t arow_off = (uint32_t)(row*ASTR + off) * 4u;
    uint32_t brow_off = (uint32_t)(128*ASTR + row*ASTR + off) * 4u;

    float acc[4][4][4];
#pragma unroll
    for (int mt=0;mt<4;mt++)
#pragma unroll
        for (int nt=0;nt<4;nt++)
#pragma unroll
            for (int i=0;i<4;i++) acc[mt][nt][i]=0.f;

    // prologue: stage 0 = chunk 0
    {
        uint32_t sa = sbase + arow_off, sb = sbase + brow_off;
#pragma unroll
        for (int i=0;i<4;i++){ cp_async16(sa + i*16, Xr + 4*i); cp_async16(sb + i*16, Wr2 + 4*i); }
        asm volatile("cp.async.commit_group;" ::: "memory");
    }

#pragma unroll 1
    for (int kc=0; kc<8; kc++){
        if (kc < 7){
            int sn = (kc+1) % 3;
            uint32_t sa = sbase + (uint32_t)(sn*STG)*4u + arow_off;
            uint32_t sb = sbase + (uint32_t)(sn*STG)*4u + brow_off;
            const float* xs = Xr  + (kc+1)*32;
            const float* ws = Wr2 + (kc+1)*32;
#pragma unroll
            for (int i=0;i<4;i++){ cp_async16(sa + i*16, xs + 4*i); cp_async16(sb + i*16, ws + 4*i); }
            asm volatile("cp.async.commit_group;" ::: "memory");
            asm volatile("cp.async.wait_group 1;" ::: "memory");
        } else {
            asm volatile("cp.async.wait_group 0;" ::: "memory");
        }
        __syncthreads();
        int s = kc % 3;
        const uint32_t* Ab = (const uint32_t*)(dyn_smem + s*STG) + (r0+g)*ASTR + tig;
        const uint32_t* Bb = (const uint32_t*)(dyn_smem + s*STG) + 128*ASTR + (n0l+g)*ASTR + tig;
#pragma unroll
        for (int kk=0; kk<4; kk++){
            int kb = kk*8;
            uint32_t af[4][4];
#pragma unroll
            for (int mt=0;mt<4;mt++){
                af[mt][0] = Ab[(mt*16    )*ASTR + kb];
                af[mt][1] = Ab[(mt*16 + 8)*ASTR + kb];
                af[mt][2] = Ab[(mt*16    )*ASTR + kb + 4];
                af[mt][3] = Ab[(mt*16 + 8)*ASTR + kb + 4];
            }
            uint32_t bf[4][2];
#pragma unroll
            for (int nt=0;nt<4;nt++){
                bf[nt][0] = Bb[(nt*8)*ASTR + kb];
                bf[nt][1] = Bb[(nt*8)*ASTR + kb + 4];
            }
#pragma unroll
            for (int mt=0;mt<4;mt++){
#pragma unroll
                for (int nt=0;nt<4;nt++){
                    asm volatile(
                        "mma.sync.aligned.m16n8k8.row.col.f32.tf32.tf32.f32 "
                        "{%0,%1,%2,%3}, {%4,%5,%6,%7}, {%8,%9}, {%0,%1,%2,%3};"
                        : "+f"(acc[mt][nt][0]), "+f"(acc[mt][nt][1]),
                          "+f"(acc[mt][nt][2]), "+f"(acc[mt][nt][3])
                        : "r"(af[mt][0]), "r"(af[mt][1]), "r"(af[mt][2]), "r"(af[mt][3]),
                          "r"(bf[nt][0]), "r"(bf[nt][1]));
                }
            }
        }
    }

    int q = q0 + warpM;
#pragma unroll
    for (int nt=0; nt<4; nt++){
#pragma unroll
        for (int hc=0; hc<2; hc++){
            int col = nh*128 + n0l + nt*8 + 2*tig + hc;
            float bias = __ldg(&b2[col]);
            float mx=-3.402823466e38f, mn=3.402823466e38f, sum=0.f, sq=0.f;
#pragma unroll
            for (int mt=0;mt<4;mt++){
                float h0 = acc[mt][nt][hc]   + bias;
                float h1 = acc[mt][nt][2+hc] + bias;
                mx=fmaxf(mx,fmaxf(h0,h1)); mn=fminf(mn,fminf(h0,h1));
                sum += h0 + h1; sq = fmaf(h0,h0,sq); sq = fmaf(h1,h1,sq);
            }
#pragma unroll
            for (int off2=4; off2<=16; off2<<=1){
                mx  = fmaxf(mx,  __shfl_xor_sync(0xffffffffu, mx,  off2));
                mn  = fminf(mn,  __shfl_xor_sync(0xffffffffu, mn,  off2));
                sum = sum +      __shfl_xor_sync(0xffffffffu, sum, off2);
                sq  = sq +       __shfl_xor_sync(0xffffffffu, sq,  off2);
            }
            if (g == 0){
                g_mx[(size_t)q*CC + col] = mx;
                g_mn[(size_t)q*CC + col] = mn;
                atomicAdd(&g_sum2[col], sum);
                atomicAdd(&g_sq2[col],  sq);
            }
        }
    }
}

// ---------------- BN2 + ReLU + maxpool + outputs ----------------
__global__ __launch_bounds__(256) void k_out(const float* __restrict__ pos,
                                             const float* __restrict__ gamma2,
                                             const float* __restrict__ beta2,
                                             float* __restrict__ out){
    int q = blockIdx.x, t = threadIdx.x, b = q/SS;
    int o = t;
    float mean = g_sum2[o]*(1.0f/MTOT);
    float var  = g_sq2[o]*(1.0f/MTOT) - mean*mean;
    float a    = gamma2[o]*rsqrtf(var + EPSF);
    float cc   = beta2[o] - mean*a;
    float v = (a>=0.f) ? fmaf(a, g_mx[(size_t)q*CC+o], cc)
                       : fmaf(a, g_mn[(size_t)q*CC+o], cc);
    out[(size_t)BB*SS*3 + (size_t)q*CC + o] = fmaxf(v, 0.f);
    if (t < 3){
        int cent = g_cent[q];
        out[(size_t)q*3 + t] = pos[(size_t)(b*NN + cent)*3 + t];
    }
}

// ---------------- launch ----------------
extern "C" void kernel_launch(void* const* d_in, const int* in_sizes, int n_in,
                              void* d_out, int out_size){
    const float* pos    = (const float*)d_in[0];
    const float* feat   = (const float*)d_in[1];
    const float* W1     = (const float*)d_in[2];
    const float* b1     = (const float*)d_in[3];
    const float* gamma1 = (const float*)d_in[4];
    const float* beta1  = (const float*)d_in[5];
    const float* W2     = (const float*)d_in[6];
    const float* b2     = (const float*)d_in[7];
    const float* gamma2 = (const float*)d_in[8];
    const float* beta2  = (const float*)d_in[9];
    float* out = (float*)d_out;

    const int mega1_smem = 256 + NN*3*4 + SS*4 + (NN/32)*4 + 64;          // ~54 KB
    const int gemm2_smem = 3*STG*sizeof(float);                           // 110592 B
    cudaFuncSetAttribute(k_mega1,  cudaFuncAttributeMaxDynamicSharedMemorySize, mega1_smem);
    cudaFuncSetAttribute(k_gemm2m, cudaFuncAttributeMaxDynamicSharedMemorySize, gemm2_smem);

    k_mega1 <<<4 + (BB*NN)/16 + 1, 512, mega1_smem>>>(pos, feat, W1, W2); // 1
    k_qgemm <<<(BB*SS)/16, 256>>>(feat, W1);                              // 2
    k_knns  <<<BB*SS, 256>>>(pos, b1);                                    // 3
    k_xbuild<<<BB*SS, 256>>>(b1, gamma1, beta1);                          // 4 -> profiled
    k_gemm2m<<<BB*SS, 256, gemm2_smem>>>(b2);                             // 5
    k_out   <<<BB*SS, 256>>>(pos, gamma2, beta2, out);                    // 6
}